// round 1
// baseline (speedup 1.0000x reference)
#include <cuda_runtime.h>
#include <cuda_bf16.h>

// Problem constants (fixed by the dataset)
#define B 8
#define L 2048
#define H 1024
#define C 64

// Scratch: per-position projection proj[b*L + l] = dot(feature[b,l,:], w)
__device__ float g_proj[B * L];

// ---------------------------------------------------------------------------
// Kernel 1: proj[b,l] = sum_h feature[b,l,h] * w[h]
// One warp per row. 8 warps (256 threads) per block. Grid = B*L/8 = 2048.
// Each thread: 8 float4 loads of feature (coalesced, MLP=8) vs smem-cached w.
// ---------------------------------------------------------------------------
__global__ __launch_bounds__(256) void proj_kernel(
    const float* __restrict__ feature,   // [B*L, H]
    const float* __restrict__ fc_weight, // [H]
    float* __restrict__ proj)            // [B*L]
{
    __shared__ float sw[H];
    const int tid = threadIdx.x;
    // Stage weights to smem (4 KB), once per block
    #pragma unroll
    for (int i = tid; i < H; i += 256) sw[i] = fc_weight[i];
    __syncthreads();

    const int warp = tid >> 5;
    const int lane = tid & 31;
    const int row  = blockIdx.x * 8 + warp;  // 0 .. B*L-1

    const float4* __restrict__ f4 = reinterpret_cast<const float4*>(
        feature + (size_t)row * H);
    const float4* __restrict__ w4 = reinterpret_cast<const float4*>(sw);

    float acc = 0.0f;
    #pragma unroll
    for (int i = 0; i < 8; i++) {
        const int idx = i * 32 + lane;      // float4 index 0..255 (H/4)
        float4 v = f4[idx];
        float4 w = w4[idx];
        acc = fmaf(v.x, w.x, acc);
        acc = fmaf(v.y, w.y, acc);
        acc = fmaf(v.z, w.z, acc);
        acc = fmaf(v.w, w.w, acc);
    }
    // Warp reduction
    #pragma unroll
    for (int o = 16; o > 0; o >>= 1)
        acc += __shfl_xor_sync(0xFFFFFFFFu, acc, o);

    if (lane == 0) proj[row] = acc;
}

// ---------------------------------------------------------------------------
// Kernel 2: out[b*C + c] = mean(proj[b, src..end]) + bias
// One warp per span. 512 spans -> 8 warps/block, grid = 64.
// proj is tiny (64 KB) and freshly written -> L2 hits.
// ---------------------------------------------------------------------------
__global__ __launch_bounds__(256) void span_kernel(
    const float* __restrict__ proj,          // [B*L]
    const int*   __restrict__ position_list, // [B*C*2]
    const float* __restrict__ fc_bias,       // [1]
    float* __restrict__ out)                 // [B*C]
{
    const int tid  = threadIdx.x;
    const int warp = tid >> 5;
    const int lane = tid & 31;
    const int span = blockIdx.x * 8 + warp;  // 0 .. B*C-1
    const int b    = span / C;

    const int src = position_list[span * 2 + 0];
    const int end = position_list[span * 2 + 1];
    const int cnt = end - src + 1;           // >= 1 (sorted, inclusive)

    const float* __restrict__ p = proj + b * L;
    float acc = 0.0f;
    for (int l = src + lane; l <= end; l += 32)
        acc += p[l];

    #pragma unroll
    for (int o = 16; o > 0; o >>= 1)
        acc += __shfl_xor_sync(0xFFFFFFFFu, acc, o);

    if (lane == 0)
        out[span] = acc / (float)cnt + fc_bias[0];
}

// ---------------------------------------------------------------------------
extern "C" void kernel_launch(void* const* d_in, const int* in_sizes, int n_in,
                              void* d_out, int out_size) {
    const float* feature       = (const float*)d_in[0];  // [B,L,H] f32
    const float* fc_weight     = (const float*)d_in[1];  // [1,H]   f32
    const float* fc_bias       = (const float*)d_in[2];  // [1]     f32
    const int*   position_list = (const int*)  d_in[3];  // [B,C,2] i32
    float* out = (float*)d_out;                          // [B*C,1] f32

    float* proj;
    cudaGetSymbolAddress((void**)&proj, g_proj);

    proj_kernel<<<(B * L) / 8, 256>>>(feature, fc_weight, proj);
    span_kernel<<<(B * C) / 8, 256>>>(proj, position_list, fc_bias, out);
}

// round 2
// speedup vs baseline: 1.1750x; 1.1750x over previous
#include <cuda_runtime.h>
#include <cuda_bf16.h>

// Problem constants (fixed by the dataset)
#define B 8
#define L 2048
#define H 1024
#define C 64

// Scratch: per-position projection proj[b*L + l] = dot(feature[b,l,:], w)
__device__ float g_proj[B * L];

// ---------------------------------------------------------------------------
// Kernel 1: proj[b,l] = sum_h feature[b,l,h] * w[h]
// One warp per row. 8 warps (256 threads) per block. Grid = B*L/8 = 2048.
// Each thread: 8 independent float4 loads (MLP=8), FMA vs smem-cached w.
// This kernel is DRAM-bound (64 MB read) — at the ~8 us floor.
// ---------------------------------------------------------------------------
__global__ __launch_bounds__(256) void proj_kernel(
    const float* __restrict__ feature,   // [B*L, H]
    const float* __restrict__ fc_weight, // [H]
    float* __restrict__ proj)            // [B*L]
{
    __shared__ float sw[H];
    const int tid = threadIdx.x;
    #pragma unroll
    for (int i = tid; i < H; i += 256) sw[i] = fc_weight[i];
    __syncthreads();

    const int warp = tid >> 5;
    const int lane = tid & 31;
    const int row  = blockIdx.x * 8 + warp;  // 0 .. B*L-1

    const float4* __restrict__ f4 = reinterpret_cast<const float4*>(
        feature + (size_t)row * H);
    const float4* __restrict__ w4 = reinterpret_cast<const float4*>(sw);

    float acc = 0.0f;
    #pragma unroll
    for (int i = 0; i < 8; i++) {
        const int idx = i * 32 + lane;      // float4 index 0..255 (H/4)
        float4 v = f4[idx];
        float4 w = w4[idx];
        acc = fmaf(v.x, w.x, acc);
        acc = fmaf(v.y, w.y, acc);
        acc = fmaf(v.z, w.z, acc);
        acc = fmaf(v.w, w.w, acc);
    }
    #pragma unroll
    for (int o = 16; o > 0; o >>= 1)
        acc += __shfl_xor_sync(0xFFFFFFFFu, acc, o);

    if (lane == 0) proj[row] = acc;
}

// ---------------------------------------------------------------------------
// Kernel 2: out[span] = mean(proj[b, src..end]) + bias
// ONE BLOCK (256 threads) per span -> grid = 512, single wave across SMs.
// Max span length 2048 -> at most 8 strided loads/thread; the loop is
// bounded and unrolled so loads issue back-to-back (MLP up to 8), hiding
// L2 latency instead of serializing it (the R1 bottleneck).
// ---------------------------------------------------------------------------
__global__ __launch_bounds__(256) void span_kernel(
    const float* __restrict__ proj,          // [B*L]
    const int*   __restrict__ position_list, // [B*C*2]
    const float* __restrict__ fc_bias,       // [1]
    float* __restrict__ out)                 // [B*C]
{
    const int span = blockIdx.x;             // 0 .. B*C-1
    const int tid  = threadIdx.x;
    const int b    = span >> 6;              // span / C

    const int src = position_list[span * 2 + 0];
    const int end = position_list[span * 2 + 1];
    const int cnt = end - src + 1;           // >= 1 (sorted, inclusive)

    const float* __restrict__ p = proj + b * L;

    // Bounded, fully unrolled accumulation: l = src + tid + k*256, k=0..7
    float acc = 0.0f;
    #pragma unroll
    for (int k = 0; k < 8; k++) {
        const int l = src + tid + k * 256;
        if (l <= end) acc += p[l];
    }

    // Block reduction: warp shuffle, then 8 partials through smem
    #pragma unroll
    for (int o = 16; o > 0; o >>= 1)
        acc += __shfl_xor_sync(0xFFFFFFFFu, acc, o);

    __shared__ float swarp[8];
    const int warp = tid >> 5;
    const int lane = tid & 31;
    if (lane == 0) swarp[warp] = acc;
    __syncthreads();

    if (warp == 0) {
        float v = (lane < 8) ? swarp[lane] : 0.0f;
        #pragma unroll
        for (int o = 4; o > 0; o >>= 1)
            v += __shfl_xor_sync(0xFFFFFFFFu, v, o);
        if (lane == 0)
            out[span] = v / (float)cnt + fc_bias[0];
    }
}

// ---------------------------------------------------------------------------
extern "C" void kernel_launch(void* const* d_in, const int* in_sizes, int n_in,
                              void* d_out, int out_size) {
    const float* feature       = (const float*)d_in[0];  // [B,L,H] f32
    const float* fc_weight     = (const float*)d_in[1];  // [1,H]   f32
    const float* fc_bias       = (const float*)d_in[2];  // [1]     f32
    const int*   position_list = (const int*)  d_in[3];  // [B,C,2] i32
    float* out = (float*)d_out;                          // [B*C,1] f32

    float* proj;
    cudaGetSymbolAddress((void**)&proj, g_proj);

    proj_kernel<<<(B * L) / 8, 256>>>(feature, fc_weight, proj);
    span_kernel<<<B * C, 256>>>(proj, position_list, fc_bias, out);
}